// round 16
// baseline (speedup 1.0000x reference)
#include <cuda_runtime.h>

// B=64, T=512, E=8192
// out[b][j] = (1/count) * sum_{r=r0}^{511} x[b*T*E + (j+512) + r*8191]
//   r0 = max(0, j - 7679), count = 512 - r0, j in [0, 8190].
//
// Persistent-CTA version of the fused intra-CTA r-split kernel:
// 296 resident CTAs (2/SM x 148) of 1024 threads; each loops round-robin
// over the 4096 (jt, b) tiles. Tile body: 128 j-columns x 8 r-slices of 64
// rows; slices 1..7 stash partials in smem; slice 0 combines and writes.
// Removes per-wave CTA setup and shrinks the drain skew to <= 1 tile.

#define B_DIM 64
#define T_DIM 512
#define E_DIM 8192
#define OUT_COLS (E_DIM - 1)          // 8191
#define ROW_STRIDE (E_DIM - 1)        // 8191
#define J_FULL (E_DIM - T_DIM - 1)    // 7679
#define JCOLS 128                     // j per tile
#define NQ 8                          // r-slices per tile
#define BLOCK (JCOLS * NQ)            // 1024 threads
#define JTILES (E_DIM / JCOLS)        // 64
#define FULL_TILES 60                 // jt 0..59: j <= 7679 (full count)
#define R_Q (T_DIM / NQ)              // 64 rows per slice
#define R_H (R_Q / 2)                 // 32 rows per stream
#define H_OFF ((unsigned)(R_H * ROW_STRIDE))
#define NTILES (JTILES * B_DIM)       // 4096
#define NCTAS 296                     // 2 per SM x 148 SMs

__global__ __launch_bounds__(BLOCK, 2) void antidiag_mean_kernel(
    const float* __restrict__ x, float* __restrict__ out)
{
    __shared__ float s_part[(NQ - 1) * JCOLS];   // 3.5 KB

    const int tid  = threadIdx.x;
    const int jcol = tid & (JCOLS - 1);
    const int q    = tid >> 7;                   // 0..7
    const int rbeg = q * R_Q;

    for (int tile = blockIdx.x; tile < NTILES; tile += NCTAS) {
        const int jt = tile & (JTILES - 1);
        const int b  = tile >> 6;                // tile / JTILES
        const int j  = jt * JCOLS + jcol;
        const bool valid = (j < OUT_COLS);

        float s = 0.0f;
        if (valid) {
            const float* __restrict__ p =
                x + (size_t)b * T_DIM * E_DIM + (size_t)(j + T_DIM);
            if (jt < FULL_TILES) {
                // hot path: full slice, two 32-row streams, unroll 8
                // -> 16 independent LDGs per scoreboard window.
                const float* ph = p + (size_t)rbeg * ROW_STRIDE;
                float s0 = 0.f, s1 = 0.f;
                #pragma unroll 8
                for (int r = 0; r < R_H; ++r) {
                    const unsigned off = (unsigned)(r * ROW_STRIDE);
                    s0 += ph[off];
                    s1 += ph[off + H_OFF];
                }
                s = s0 + s1;
            } else {
                // ragged tiles (j in [7680, 8190]): clamp slice start to r0
                const int r0 = j - J_FULL;       // >= 1 here
                const int rs = (r0 > rbeg) ? r0 : rbeg;
                const int re = rbeg + R_Q;
                #pragma unroll 8
                for (int r = rs; r < re; ++r)
                    s += p[(unsigned)(r * ROW_STRIDE)];
            }
        }

        // slices 1..7 publish partials; slice 0 combines and writes.
        if (q > 0)
            s_part[(q - 1) * JCOLS + jcol] = s;
        __syncthreads();

        if (q == 0 && valid) {
            float acc = s;
            #pragma unroll
            for (int qq = 0; qq < NQ - 1; ++qq)
                acc += s_part[qq * JCOLS + jcol];
            const int r0 = (j > J_FULL) ? (j - J_FULL) : 0;
            out[(size_t)b * OUT_COLS + j] = acc * (1.0f / (float)(T_DIM - r0));
        }
        __syncthreads();   // protect s_part reuse on the next tile
    }
}

extern "C" void kernel_launch(void* const* d_in, const int* in_sizes, int n_in,
                              void* d_out, int out_size)
{
    const float* x = (const float*)d_in[0];
    float* out = (float*)d_out;

    dim3 block(BLOCK);
    dim3 grid(NCTAS);                // 296 persistent CTAs (2 per SM)
    antidiag_mean_kernel<<<grid, block>>>(x, out);
}